// round 14
// baseline (speedup 1.0000x reference)
#include <cuda_runtime.h>
#include <cuda_bf16.h>
#include <cstdint>

// Problem constants (fixed by the dataset)
#define B 64
#define S 8192
#define C 48
#define L 42
#define LP1 (L + 1)          // 43
#define IGNORE_LBL (-100)

#define THREADS 512
#define WARPS   (THREADS / 32)   // 16
#define NCH     4                // chunks per row
#define CHUNK   (S / NCH)        // 2048 positions; 4 consecutive per thread
#define NSEG    WARPS            // 16 warp-segments per chunk
#define NCHT    (B * NCH)        // 256 blocks

// ---------------------------------------------------------------------------
// Device-global scratch
// ---------------------------------------------------------------------------
__device__ float  g_partial[NCHT];   // per-chunk normalized partial
__device__ int    g_pcount[NCHT];    // per-chunk valid-token count
__device__ int    g_first[NCHT];     // per-chunk first valid label (-1 if none)
__device__ int    g_last[NCHT];      // per-chunk last valid label
__device__ unsigned g_ticket;        // finish counter (reset by last block)

// Gather load with 64B L2 fetch-size hint (halves DRAM fill vs 128B line).
__device__ __forceinline__ float ld_gather_64B(const float* p) {
    float v;
    asm volatile("ld.global.L2::64B.f32 %0, [%1];" : "=f"(v) : "l"(p));
    return v;
}
// L2 prefetch: request-only, no MSHR/register dependency.
__device__ __forceinline__ void prefetch_L2(const float* p) {
    asm volatile("prefetch.global.L2 [%0];" :: "l"(p));
}

// ---------------------------------------------------------------------------
// One block per (row, chunk). Thread t owns consecutive positions {4t..4t+3}.
// Gather addresses are L2-prefetched as soon as labels land; the LSE phase
// overlaps the DRAM->L2 flight; the real loads then hit L2.
// ---------------------------------------------------------------------------
__global__ __launch_bounds__(THREADS)
void crf_fused_kernel(const float* log_probs,
                      const float* __restrict__ A_scores,
                      const int*   __restrict__ labels,
                      float*       __restrict__ out) {
    const int cid  = blockIdx.x;        // chunk id
    const int b    = cid / NCH;         // batch row
    const int ch   = cid % NCH;         // chunk within row
    const int tid  = threadIdx.x;
    const int lane = tid & 31;
    const int wid  = tid >> 5;

    __shared__ float  A_sh[L + L * LP1];   // 1848 raw scores
    __shared__ float  lse_sh[LP1];         // [0..41]=trans rows, [42]=start
    __shared__ int    seg_first[NSEG];
    __shared__ int    seg_last[NSEG];
    __shared__ float  red[WARPS];
    __shared__ int    redc[WARPS];
    __shared__ int    is_last;
    __shared__ double row_sum[B];
    __shared__ int    row_cnt[B];

    // ---- 1. issue label load (int4) first, then stage A_scores ----
    const int4* lab = (const int4*)(labels + (size_t)b * S + (size_t)ch * CHUNK);
    int4 yy = __ldg(lab + tid);            // positions 4t .. 4t+3

    #pragma unroll
    for (int i = tid; i < L + L * LP1; i += THREADS) A_sh[i] = A_scores[i];

    // ---- 2. prefetch all 4 gather lines into L2 the moment labels land ----
    const float* lpb = log_probs + (size_t)b * S * C + (size_t)ch * CHUNK * C
                     + (size_t)(4 * tid) * C;
    int  y[4]  = {yy.x, yy.y, yy.z, yy.w};
    bool v[4];
    #pragma unroll
    for (int i = 0; i < 4; i++) {
        v[i] = (y[i] != IGNORE_LBL);
        if (v[i]) prefetch_L2(lpb + i * C + y[i]);
    }

    __syncthreads();   // A_sh ready

    // ---- 3. 43 log-sum-exps (warp w: rows w, w+16, w+32) — overlaps
    //         the DRAM->L2 prefetch flight ----
    #pragma unroll
    for (int rr = 0; rr < 3; rr++) {
        int r = wid + rr * WARPS;
        if (r <= L) {
            int n = (r == L) ? L : LP1;
            const float* row = (r == L) ? A_sh : (A_sh + L + r * LP1);
            float v0 = (lane < n)      ? row[lane]      : -1e30f;
            float v1 = (lane + 32 < n) ? row[lane + 32] : -1e30f;
            float m = fmaxf(v0, v1);
            #pragma unroll
            for (int o = 16; o > 0; o >>= 1)
                m = fmaxf(m, __shfl_xor_sync(0xffffffffu, m, o));
            float s = ((lane < n) ? __expf(v0 - m) : 0.f)
                    + ((lane + 32 < n) ? __expf(v1 - m) : 0.f);
            #pragma unroll
            for (int o = 16; o > 0; o >>= 1)
                s += __shfl_xor_sync(0xffffffffu, s, o);
            if (lane == 0) lse_sh[r] = m + __logf(s);
        }
    }
    __syncthreads();   // lse_sh ready

    // ---- 4. real gathers (should now hit L2), 64B hint ----
    float e[4];
    #pragma unroll
    for (int i = 0; i < 4; i++)
        e[i] = v[i] ? ld_gather_64B(lpb + i * C + y[i]) : 0.0f;

    // ---- 5. thread-local transition chain (skips invalids) ----
    float local = 0.0f;
    int   cnt   = 0;
    int   prev = -1, firstv = -1;
    #pragma unroll
    for (int i = 0; i < 4; i++) {
        if (v[i]) {
            cnt++;
            if (prev >= 0) local += A_sh[L + (prev - 1) * LP1 + (y[i] - 1)] - lse_sh[prev - 1];
            else           firstv = y[i];
            prev = y[i];
        }
    }
    const int lastv = prev;

    // ---- 6. cross-thread chain + warp-segment endpoints (one ballot) ----
    bool ne = (firstv >= 0);
    unsigned m = __ballot_sync(0xffffffffu, ne);
    unsigned rest = m & (0xFFFFFFFEu << lane);       // nonempty lanes strictly after me
    int partner = rest ? (__ffs(rest) - 1) : -1;
    int pfirst  = __shfl_sync(0xffffffffu, firstv, partner & 31);
    if (ne && partner >= 0)
        local += A_sh[L + (lastv - 1) * LP1 + (pfirst - 1)] - lse_sh[lastv - 1];

    int flane = __ffs(m) - 1;
    int llane = 31 - __clz(m | 1u);
    int yf = __shfl_sync(0xffffffffu, firstv, flane & 31);
    int yl = __shfl_sync(0xffffffffu, lastv,  llane & 31);
    if (lane == 0) {
        seg_first[wid] = m ? yf : -1;
        seg_last[wid]  = m ? yl : -1;
    }
    __syncthreads();   // seg arrays ready

    // ---- 7. warp-boundary stitching (warp 0, 16 segments, one ballot) ----
    if (wid == 0) {
        bool sne = (lane < NSEG) && (seg_first[lane] >= 0);
        unsigned sm = __ballot_sync(0xffffffffu, sne);
        if (sne) {
            unsigned low = sm & ((1u << lane) - 1u);
            if (low) {
                int pred = 31 - __clz(low);
                int a = seg_last[pred], c2 = seg_first[lane];
                local += A_sh[L + (a - 1) * LP1 + (c2 - 1)] - lse_sh[a - 1];
            }
        }
        if (lane == 0) {
            g_first[cid] = sm ? seg_first[__ffs(sm) - 1] : -1;
            g_last[cid]  = sm ? seg_last[31 - __clz(sm)] : -1;
        }
    }

    // ---- 8. fold emissions, block reduce (float) ----
    local += (e[0] + e[1]) + (e[2] + e[3]);
    #pragma unroll
    for (int o = 16; o > 0; o >>= 1) {
        local += __shfl_down_sync(0xffffffffu, local, o);
        cnt   += __shfl_down_sync(0xffffffffu, cnt, o);
    }
    if (lane == 0) { red[wid] = local; redc[wid] = cnt; }
    __syncthreads();
    if (wid == 0) {
        float vv = (lane < WARPS) ? red[lane] : 0.0f;
        int   cc = (lane < WARPS) ? redc[lane] : 0;
        #pragma unroll
        for (int o = 8; o > 0; o >>= 1) {
            vv += __shfl_down_sync(0xffffffffu, vv, o);
            cc += __shfl_down_sync(0xffffffffu, cc, o);
        }
        if (lane == 0) {
            g_partial[cid] = vv;
            g_pcount[cid]  = cc;
            __threadfence();
            unsigned t = atomicAdd(&g_ticket, 1u);
            is_last = (t == NCHT - 1) ? 1 : 0;
        }
    }
    __syncthreads();

    // ---- 9. last block: stitch chunk boundaries + start/final, finalize ----
    if (is_last) {
        __threadfence();
        if (tid < B) {
            double s = 0.0; int c = 0, prv = -1, f0 = -1;
            #pragma unroll
            for (int k = 0; k < NCH; k++) {
                int idx = tid * NCH + k;
                s += (double)g_partial[idx];
                c += g_pcount[idx];
                int f = g_first[idx];
                if (f >= 0) {
                    if (prv >= 0)
                        s += (double)(A_sh[L + (prv - 1) * LP1 + (f - 1)] - lse_sh[prv - 1]);
                    else f0 = f;
                    prv = g_last[idx];
                }
            }
            if (f0 >= 0) {
                s += (double)(A_sh[f0 - 1] - lse_sh[L]);                        // start
                s += (double)(A_sh[L + (prv - 1) * LP1 + L] - lse_sh[prv - 1]); // final
            }
            row_sum[tid] = s;
            row_cnt[tid] = c;
        }
        __syncthreads();
        if (wid == 0) {
            double s = row_sum[lane] + row_sum[lane + 32];
            int    c = row_cnt[lane] + row_cnt[lane + 32];
            #pragma unroll
            for (int o = 16; o > 0; o >>= 1) {
                s += __shfl_down_sync(0xffffffffu, s, o);
                c += __shfl_down_sync(0xffffffffu, c, o);
            }
            if (lane == 0) {
                out[0] = (float)(s / (double)c);
                g_ticket = 0;    // reset for graph replay
            }
        }
    }
}

// ---------------------------------------------------------------------------
// Launch
// ---------------------------------------------------------------------------
extern "C" void kernel_launch(void* const* d_in, const int* in_sizes, int n_in,
                              void* d_out, int out_size) {
    const float* log_probs = (const float*)d_in[0];   // (B, S, C) f32
    const float* A_scores  = (const float*)d_in[1];   // (N_ARCS,) f32
    const int*   labels    = (const int*)d_in[2];     // (B, S) i32
    float* out = (float*)d_out;

    crf_fused_kernel<<<NCHT, THREADS>>>(log_probs, A_scores, labels, out);
}

// round 15
// speedup vs baseline: 1.0519x; 1.0519x over previous
#include <cuda_runtime.h>
#include <cuda_bf16.h>
#include <cstdint>

// Problem constants (fixed by the dataset)
#define B 64
#define S 8192
#define C 48
#define L 42
#define LP1 (L + 1)          // 43
#define IGNORE_LBL (-100)

#define THREADS 512
#define WARPS   (THREADS / 32)   // 16
#define NCH     4                // chunks per row
#define CHUNK   (S / NCH)        // 2048 positions; 4 consecutive per thread
#define NSEG    WARPS            // 16 warp-segments per chunk
#define NCHT    (B * NCH)        // 256 blocks

// ---------------------------------------------------------------------------
// Device-global scratch
// ---------------------------------------------------------------------------
__device__ float  g_partial[NCHT];   // per-chunk normalized partial
__device__ int    g_pcount[NCHT];    // per-chunk valid-token count
__device__ int    g_first[NCHT];     // per-chunk first valid label (-1 if none)
__device__ int    g_last[NCHT];      // per-chunk last valid label
__device__ unsigned g_ticket;        // finish counter (reset by last block)

__device__ __forceinline__ uint32_t smem_u32(const void* p) {
    uint32_t a;
    asm("{ .reg .u64 t; cvta.to.shared.u64 t, %1; cvt.u32.u64 %0, t; }"
        : "=r"(a) : "l"(p));
    return a;
}
// 4-byte async copy global->shared (LDGSTS): deep outstanding-miss budget,
// no register/scoreboard occupancy while in flight.
__device__ __forceinline__ void cp_async_4(uint32_t dst_smem, const float* src) {
    asm volatile("cp.async.ca.shared.global [%0], [%1], 4;"
                 :: "r"(dst_smem), "l"(src));
}
__device__ __forceinline__ void cp_async_commit() {
    asm volatile("cp.async.commit_group;");
}
__device__ __forceinline__ void cp_async_wait0() {
    asm volatile("cp.async.wait_group 0;");
}

// ---------------------------------------------------------------------------
// One block per (row, chunk). Thread t owns consecutive positions {4t..4t+3}.
// Emission gathers go through cp.async into shared; the LSE phase overlaps
// the flight.
// ---------------------------------------------------------------------------
__global__ __launch_bounds__(THREADS)
void crf_fused_kernel(const float* log_probs,
                      const float* __restrict__ A_scores,
                      const int*   __restrict__ labels,
                      float*       __restrict__ out) {
    const int cid  = blockIdx.x;        // chunk id
    const int b    = cid / NCH;         // batch row
    const int ch   = cid % NCH;         // chunk within row
    const int tid  = threadIdx.x;
    const int lane = tid & 31;
    const int wid  = tid >> 5;

    __shared__ float  A_sh[L + L * LP1];   // 1848 raw scores
    __shared__ float  lse_sh[LP1];         // [0..41]=trans rows, [42]=start
    __shared__ float  emi_sh[4 * THREADS]; // staged gathers: [i*THREADS + tid]
    __shared__ int    seg_first[NSEG];
    __shared__ int    seg_last[NSEG];
    __shared__ float  red[WARPS];
    __shared__ int    redc[WARPS];
    __shared__ int    is_last;
    __shared__ double row_sum[B];
    __shared__ int    row_cnt[B];

    // ---- 1. issue label load (int4) first, then stage A_scores ----
    const int4* lab = (const int4*)(labels + (size_t)b * S + (size_t)ch * CHUNK);
    int4 yy = __ldg(lab + tid);            // positions 4t .. 4t+3

    #pragma unroll
    for (int i = tid; i < L + L * LP1; i += THREADS) A_sh[i] = A_scores[i];

    // ---- 2. issue cp.async gathers the moment labels land ----
    const float* lpb = log_probs + (size_t)b * S * C + (size_t)ch * CHUNK * C
                     + (size_t)(4 * tid) * C;
    int  y[4]  = {yy.x, yy.y, yy.z, yy.w};
    bool v[4];
    const uint32_t emi_base = smem_u32(emi_sh);
    #pragma unroll
    for (int i = 0; i < 4; i++) {
        v[i] = (y[i] != IGNORE_LBL);
        uint32_t dst = emi_base + (i * THREADS + tid) * 4u;
        if (v[i]) cp_async_4(dst, lpb + i * C + y[i]);
        else      asm volatile("st.shared.f32 [%0], 0f00000000;" :: "r"(dst));
    }
    cp_async_commit();

    __syncthreads();   // A_sh ready (cp.async flight continues)

    // ---- 3. 43 log-sum-exps (warp w: rows w, w+16, w+32) — overlaps flight ----
    #pragma unroll
    for (int rr = 0; rr < 3; rr++) {
        int r = wid + rr * WARPS;
        if (r <= L) {
            int n = (r == L) ? L : LP1;
            const float* row = (r == L) ? A_sh : (A_sh + L + r * LP1);
            float v0 = (lane < n)      ? row[lane]      : -1e30f;
            float v1 = (lane + 32 < n) ? row[lane + 32] : -1e30f;
            float m = fmaxf(v0, v1);
            #pragma unroll
            for (int o = 16; o > 0; o >>= 1)
                m = fmaxf(m, __shfl_xor_sync(0xffffffffu, m, o));
            float s = ((lane < n) ? __expf(v0 - m) : 0.f)
                    + ((lane + 32 < n) ? __expf(v1 - m) : 0.f);
            #pragma unroll
            for (int o = 16; o > 0; o >>= 1)
                s += __shfl_xor_sync(0xffffffffu, s, o);
            if (lane == 0) lse_sh[r] = m + __logf(s);
        }
    }
    __syncthreads();   // lse_sh ready

    // ---- 4. thread-local transition chain (skips invalids) ----
    float local = 0.0f;
    int   cnt   = 0;
    int   prev = -1, firstv = -1;
    #pragma unroll
    for (int i = 0; i < 4; i++) {
        if (v[i]) {
            cnt++;
            if (prev >= 0) local += A_sh[L + (prev - 1) * LP1 + (y[i] - 1)] - lse_sh[prev - 1];
            else           firstv = y[i];
            prev = y[i];
        }
    }
    const int lastv = prev;

    // ---- 5. cross-thread chain + warp-segment endpoints (one ballot) ----
    bool ne = (firstv >= 0);
    unsigned m = __ballot_sync(0xffffffffu, ne);
    unsigned rest = m & (0xFFFFFFFEu << lane);       // nonempty lanes strictly after me
    int partner = rest ? (__ffs(rest) - 1) : -1;
    int pfirst  = __shfl_sync(0xffffffffu, firstv, partner & 31);
    if (ne && partner >= 0)
        local += A_sh[L + (lastv - 1) * LP1 + (pfirst - 1)] - lse_sh[lastv - 1];

    int flane = __ffs(m) - 1;
    int llane = 31 - __clz(m | 1u);
    int yf = __shfl_sync(0xffffffffu, firstv, flane & 31);
    int yl = __shfl_sync(0xffffffffu, lastv,  llane & 31);
    if (lane == 0) {
        seg_first[wid] = m ? yf : -1;
        seg_last[wid]  = m ? yl : -1;
    }
    __syncthreads();   // seg arrays ready

    // ---- 6. warp-boundary stitching (warp 0, 16 segments, one ballot) ----
    if (wid == 0) {
        bool sne = (lane < NSEG) && (seg_first[lane] >= 0);
        unsigned sm = __ballot_sync(0xffffffffu, sne);
        if (sne) {
            unsigned low = sm & ((1u << lane) - 1u);
            if (low) {
                int pred = 31 - __clz(low);
                int a = seg_last[pred], c2 = seg_first[lane];
                local += A_sh[L + (a - 1) * LP1 + (c2 - 1)] - lse_sh[a - 1];
            }
        }
        if (lane == 0) {
            g_first[cid] = sm ? seg_first[__ffs(sm) - 1] : -1;
            g_last[cid]  = sm ? seg_last[31 - __clz(sm)] : -1;
        }
    }

    // ---- 7. wait for gathers, fold emissions (own slots only), reduce ----
    cp_async_wait0();
    float e0, e1, e2, e3;
    {
        uint32_t a0 = emi_base + (0 * THREADS + tid) * 4u;
        uint32_t a1 = emi_base + (1 * THREADS + tid) * 4u;
        uint32_t a2 = emi_base + (2 * THREADS + tid) * 4u;
        uint32_t a3 = emi_base + (3 * THREADS + tid) * 4u;
        asm volatile("ld.shared.f32 %0, [%1];" : "=f"(e0) : "r"(a0));
        asm volatile("ld.shared.f32 %0, [%1];" : "=f"(e1) : "r"(a1));
        asm volatile("ld.shared.f32 %0, [%1];" : "=f"(e2) : "r"(a2));
        asm volatile("ld.shared.f32 %0, [%1];" : "=f"(e3) : "r"(a3));
    }
    local += (e0 + e1) + (e2 + e3);

    #pragma unroll
    for (int o = 16; o > 0; o >>= 1) {
        local += __shfl_down_sync(0xffffffffu, local, o);
        cnt   += __shfl_down_sync(0xffffffffu, cnt, o);
    }
    if (lane == 0) { red[wid] = local; redc[wid] = cnt; }
    __syncthreads();
    if (wid == 0) {
        float vv = (lane < WARPS) ? red[lane] : 0.0f;
        int   cc = (lane < WARPS) ? redc[lane] : 0;
        #pragma unroll
        for (int o = 8; o > 0; o >>= 1) {
            vv += __shfl_down_sync(0xffffffffu, vv, o);
            cc += __shfl_down_sync(0xffffffffu, cc, o);
        }
        if (lane == 0) {
            g_partial[cid] = vv;
            g_pcount[cid]  = cc;
            __threadfence();
            unsigned t = atomicAdd(&g_ticket, 1u);
            is_last = (t == NCHT - 1) ? 1 : 0;
        }
    }
    __syncthreads();

    // ---- 8. last block: stitch chunk boundaries + start/final, finalize ----
    if (is_last) {
        __threadfence();
        if (tid < B) {
            double s = 0.0; int c = 0, prv = -1, f0 = -1;
            #pragma unroll
            for (int k = 0; k < NCH; k++) {
                int idx = tid * NCH + k;
                s += (double)g_partial[idx];
                c += g_pcount[idx];
                int f = g_first[idx];
                if (f >= 0) {
                    if (prv >= 0)
                        s += (double)(A_sh[L + (prv - 1) * LP1 + (f - 1)] - lse_sh[prv - 1]);
                    else f0 = f;
                    prv = g_last[idx];
                }
            }
            if (f0 >= 0) {
                s += (double)(A_sh[f0 - 1] - lse_sh[L]);                        // start
                s += (double)(A_sh[L + (prv - 1) * LP1 + L] - lse_sh[prv - 1]); // final
            }
            row_sum[tid] = s;
            row_cnt[tid] = c;
        }
        __syncthreads();
        if (wid == 0) {
            double s = row_sum[lane] + row_sum[lane + 32];
            int    c = row_cnt[lane] + row_cnt[lane + 32];
            #pragma unroll
            for (int o = 16; o > 0; o >>= 1) {
                s += __shfl_down_sync(0xffffffffu, s, o);
                c += __shfl_down_sync(0xffffffffu, c, o);
            }
            if (lane == 0) {
                out[0] = (float)(s / (double)c);
                g_ticket = 0;    // reset for graph replay
            }
        }
    }
}

// ---------------------------------------------------------------------------
// Launch
// ---------------------------------------------------------------------------
extern "C" void kernel_launch(void* const* d_in, const int* in_sizes, int n_in,
                              void* d_out, int out_size) {
    const float* log_probs = (const float*)d_in[0];   // (B, S, C) f32
    const float* A_scores  = (const float*)d_in[1];   // (N_ARCS,) f32
    const int*   labels    = (const int*)d_in[2];     // (B, S) i32
    float* out = (float*)d_out;

    crf_fused_kernel<<<NCHT, THREADS>>>(log_probs, A_scores, labels, out);
}

// round 17
// speedup vs baseline: 1.1257x; 1.0702x over previous
#include <cuda_runtime.h>
#include <cuda_bf16.h>
#include <cstdint>

// Problem constants (fixed by the dataset)
#define B 64
#define S 8192
#define C 48
#define L 42
#define LP1 (L + 1)          // 43
#define IGNORE_LBL (-100)

#define THREADS 512
#define WARPS   (THREADS / 32)   // 16
#define NCH     4                // chunks per row
#define CHUNK   (S / NCH)        // 2048 positions; 4 consecutive per thread
#define NSEG    WARPS            // 16 warp-segments per chunk
#define NCHT    (B * NCH)        // 256 blocks

// ---------------------------------------------------------------------------
// Device-global scratch
// ---------------------------------------------------------------------------
__device__ float  g_partial[NCHT];   // per-chunk normalized partial
__device__ int    g_pcount[NCHT];    // per-chunk valid-token count
__device__ int    g_first[NCHT];     // per-chunk first valid label (-1 if none)
__device__ int    g_last[NCHT];      // per-chunk last valid label
__device__ unsigned g_ticket;        // finish counter (reset by last block)

// Gather load: L1-bypass (.cg) + 64B L2 fetch-size hint. No L1 line
// allocation -> should not consume L1-fill miss-tracking entries.
__device__ __forceinline__ float ld_gather_cg64(const float* p) {
    float v;
    asm volatile("ld.global.cg.L2::64B.f32 %0, [%1];" : "=f"(v) : "l"(p));
    return v;
}

// ---------------------------------------------------------------------------
// One block per (row, chunk). Thread t owns consecutive positions {4t..4t+3}:
// one int4 label load, thread-local transition chain, single cross-thread
// ballot chain, one segment per warp. 4 gathers in flight per thread.
// ---------------------------------------------------------------------------
__global__ __launch_bounds__(THREADS)
void crf_fused_kernel(const float* log_probs,
                      const float* __restrict__ A_scores,
                      const int*   __restrict__ labels,
                      float*       __restrict__ out) {
    const int cid  = blockIdx.x;        // chunk id
    const int b    = cid / NCH;         // batch row
    const int ch   = cid % NCH;         // chunk within row
    const int tid  = threadIdx.x;
    const int lane = tid & 31;
    const int wid  = tid >> 5;

    __shared__ float  A_sh[L + L * LP1];   // 1848 raw scores
    __shared__ float  lse_sh[LP1];         // [0..41]=trans rows, [42]=start
    __shared__ int    seg_first[NSEG];
    __shared__ int    seg_last[NSEG];
    __shared__ float  red[WARPS];
    __shared__ int    redc[WARPS];
    __shared__ int    is_last;
    __shared__ double row_sum[B];
    __shared__ int    row_cnt[B];

    // ---- 1. issue label load (int4) first, then stage A_scores ----
    const int4* lab = (const int4*)(labels + (size_t)b * S + (size_t)ch * CHUNK);
    int4 yy = __ldg(lab + tid);            // positions 4t .. 4t+3

    #pragma unroll
    for (int i = tid; i < L + L * LP1; i += THREADS) A_sh[i] = A_scores[i];
    __syncthreads();   // A_sh ready (label LDG still in flight)

    // ---- 2. 43 log-sum-exps (warp w: rows w, w+16, w+32), overlaps labels ----
    #pragma unroll
    for (int rr = 0; rr < 3; rr++) {
        int r = wid + rr * WARPS;
        if (r <= L) {
            int n = (r == L) ? L : LP1;
            const float* row = (r == L) ? A_sh : (A_sh + L + r * LP1);
            float v0 = (lane < n)      ? row[lane]      : -1e30f;
            float v1 = (lane + 32 < n) ? row[lane + 32] : -1e30f;
            float m = fmaxf(v0, v1);
            #pragma unroll
            for (int o = 16; o > 0; o >>= 1)
                m = fmaxf(m, __shfl_xor_sync(0xffffffffu, m, o));
            float s = ((lane < n) ? __expf(v0 - m) : 0.f)
                    + ((lane + 32 < n) ? __expf(v1 - m) : 0.f);
            #pragma unroll
            for (int o = 16; o > 0; o >>= 1)
                s += __shfl_xor_sync(0xffffffffu, s, o);
            if (lane == 0) lse_sh[r] = m + __logf(s);
        }
    }
    __syncthreads();   // lse_sh ready

    // ---- 3. issue all 4 emission gathers (labels landed), .cg + 64B hint ----
    const float* lpb = log_probs + (size_t)b * S * C + (size_t)ch * CHUNK * C
                     + (size_t)(4 * tid) * C;
    int  y[4]  = {yy.x, yy.y, yy.z, yy.w};
    bool v[4];
    float e[4];
    #pragma unroll
    for (int i = 0; i < 4; i++) {
        v[i] = (y[i] != IGNORE_LBL);
        e[i] = v[i] ? ld_gather_cg64(lpb + i * C + y[i]) : 0.0f;
    }

    // ---- 4. thread-local transition chain (skips invalids) ----
    float local = 0.0f;
    int   cnt   = 0;
    int   prev = -1, firstv = -1;
    #pragma unroll
    for (int i = 0; i < 4; i++) {
        if (v[i]) {
            cnt++;
            if (prev >= 0) local += A_sh[L + (prev - 1) * LP1 + (y[i] - 1)] - lse_sh[prev - 1];
            else           firstv = y[i];
            prev = y[i];
        }
    }
    const int lastv = prev;

    // ---- 5. cross-thread chain + warp-segment endpoints (one ballot) ----
    bool ne = (firstv >= 0);
    unsigned m = __ballot_sync(0xffffffffu, ne);
    unsigned rest = m & (0xFFFFFFFEu << lane);       // nonempty lanes strictly after me
    int partner = rest ? (__ffs(rest) - 1) : -1;
    int pfirst  = __shfl_sync(0xffffffffu, firstv, partner & 31);
    if (ne && partner >= 0)
        local += A_sh[L + (lastv - 1) * LP1 + (pfirst - 1)] - lse_sh[lastv - 1];

    int flane = __ffs(m) - 1;
    int llane = 31 - __clz(m | 1u);
    int yf = __shfl_sync(0xffffffffu, firstv, flane & 31);
    int yl = __shfl_sync(0xffffffffu, lastv,  llane & 31);
    if (lane == 0) {
        seg_first[wid] = m ? yf : -1;
        seg_last[wid]  = m ? yl : -1;
    }
    __syncthreads();   // seg arrays ready

    // ---- 6. warp-boundary stitching (warp 0, 16 segments, one ballot) ----
    if (wid == 0) {
        bool sne = (lane < NSEG) && (seg_first[lane] >= 0);
        unsigned sm = __ballot_sync(0xffffffffu, sne);
        if (sne) {
            unsigned low = sm & ((1u << lane) - 1u);
            if (low) {
                int pred = 31 - __clz(low);
                int a = seg_last[pred], c2 = seg_first[lane];
                local += A_sh[L + (a - 1) * LP1 + (c2 - 1)] - lse_sh[a - 1];
            }
        }
        if (lane == 0) {
            g_first[cid] = sm ? seg_first[__ffs(sm) - 1] : -1;
            g_last[cid]  = sm ? seg_last[31 - __clz(sm)] : -1;
        }
    }

    // ---- 7. fold emissions, block reduce (float) ----
    local += (e[0] + e[1]) + (e[2] + e[3]);
    #pragma unroll
    for (int o = 16; o > 0; o >>= 1) {
        local += __shfl_down_sync(0xffffffffu, local, o);
        cnt   += __shfl_down_sync(0xffffffffu, cnt, o);
    }
    if (lane == 0) { red[wid] = local; redc[wid] = cnt; }
    __syncthreads();
    if (wid == 0) {
        float vv = (lane < WARPS) ? red[lane] : 0.0f;
        int   cc = (lane < WARPS) ? redc[lane] : 0;
        #pragma unroll
        for (int o = 8; o > 0; o >>= 1) {
            vv += __shfl_down_sync(0xffffffffu, vv, o);
            cc += __shfl_down_sync(0xffffffffu, cc, o);
        }
        if (lane == 0) {
            g_partial[cid] = vv;
            g_pcount[cid]  = cc;
            __threadfence();
            unsigned t = atomicAdd(&g_ticket, 1u);
            is_last = (t == NCHT - 1) ? 1 : 0;
        }
    }
    __syncthreads();

    // ---- 8. last block: stitch chunk boundaries + start/final, finalize ----
    if (is_last) {
        __threadfence();
        if (tid < B) {
            double s = 0.0; int c = 0, prv = -1, f0 = -1;
            #pragma unroll
            for (int k = 0; k < NCH; k++) {
                int idx = tid * NCH + k;
                s += (double)g_partial[idx];
                c += g_pcount[idx];
                int f = g_first[idx];
                if (f >= 0) {
                    if (prv >= 0)
                        s += (double)(A_sh[L + (prv - 1) * LP1 + (f - 1)] - lse_sh[prv - 1]);
                    else f0 = f;
                    prv = g_last[idx];
                }
            }
            if (f0 >= 0) {
                s += (double)(A_sh[f0 - 1] - lse_sh[L]);                        // start
                s += (double)(A_sh[L + (prv - 1) * LP1 + L] - lse_sh[prv - 1]); // final
            }
            row_sum[tid] = s;
            row_cnt[tid] = c;
        }
        __syncthreads();
        if (wid == 0) {
            double s = row_sum[lane] + row_sum[lane + 32];
            int    c = row_cnt[lane] + row_cnt[lane + 32];
            #pragma unroll
            for (int o = 16; o > 0; o >>= 1) {
                s += __shfl_down_sync(0xffffffffu, s, o);
                c += __shfl_down_sync(0xffffffffu, c, o);
            }
            if (lane == 0) {
                out[0] = (float)(s / (double)c);
                g_ticket = 0;    // reset for graph replay
            }
        }
    }
}

// ---------------------------------------------------------------------------
// Launch
// ---------------------------------------------------------------------------
extern "C" void kernel_launch(void* const* d_in, const int* in_sizes, int n_in,
                              void* d_out, int out_size) {
    const float* log_probs = (const float*)d_in[0];   // (B, S, C) f32
    const float* A_scores  = (const float*)d_in[1];   // (N_ARCS,) f32
    const int*   labels    = (const int*)d_in[2];     // (B, S) i32
    float* out = (float*)d_out;

    crf_fused_kernel<<<NCHT, THREADS>>>(log_probs, A_scores, labels, out);
}